// round 3
// baseline (speedup 1.0000x reference)
#include <cuda_runtime.h>
#include <math.h>

#define BATCH 4
#define SEQ   1024
#define EMB   768
#define NHEAD 12
#define HDIM  64
#define MLPD  3072
#define NROWS (BATCH*SEQ)   // 4096
#define QKVW  (3*EMB)       // 2304

// ---- scratch (device globals: no allocation allowed) ----
__device__ float g_h   [NROWS*EMB];    // LN1 output (also reused for LN2 output)
__device__ float g_qkv [NROWS*QKVW];
__device__ float g_attn[NROWS*EMB];
__device__ float g_x2  [NROWS*EMB];    // x + h + attn_proj
__device__ float g_mid [NROWS*MLPD];

// ======================= LayerNorm =======================
// one block (256 thr) per row of 768
__global__ __launch_bounds__(256) void ln_kernel(
    const float* __restrict__ x, const float* __restrict__ g,
    const float* __restrict__ b, float* __restrict__ out)
{
    int row = blockIdx.x;
    const float* xr = x + (size_t)row * EMB;
    float* orow = out + (size_t)row * EMB;
    int t = threadIdx.x;

    float v[3];
    float s = 0.f, s2 = 0.f;
#pragma unroll
    for (int i = 0; i < 3; i++) {
        v[i] = xr[t + i * 256];
        s  += v[i];
        s2 += v[i] * v[i];
    }
    // warp reduce
#pragma unroll
    for (int o = 16; o; o >>= 1) {
        s  += __shfl_xor_sync(0xffffffffu, s,  o);
        s2 += __shfl_xor_sync(0xffffffffu, s2, o);
    }
    __shared__ float red[2][8];
    if ((t & 31) == 0) { red[0][t >> 5] = s; red[1][t >> 5] = s2; }
    __syncthreads();
    s = 0.f; s2 = 0.f;
#pragma unroll
    for (int i = 0; i < 8; i++) { s += red[0][i]; s2 += red[1][i]; }

    const float inv_n = 1.0f / (float)EMB;
    float mu  = s * inv_n;
    float var = fmaxf(s2 * inv_n - mu * mu, 0.f);
    float rs  = rsqrtf(var + 1e-5f);
#pragma unroll
    for (int i = 0; i < 3; i++) {
        int c = t + i * 256;
        orow[c] = (v[i] - mu) * rs * g[c] + b[c];
    }
}

// ======================= SGEMM =======================
// C[M,N] = A[M,K] @ B[K,N]  (all row-major), 128x128x16 tile, 8x8 microtile
// EPI: 0 = none
//      1 = +bias[c] + r1[idx] + r2[idx]   (out-proj: x + h + attn)
//      2 = gelu_exact(+bias[c])           (fc1)
//      3 = +bias[c] + r1[idx]             (fc2 residual)
__device__ __forceinline__ float gelu_exact(float v) {
    return 0.5f * v * (1.0f + erff(v * 0.70710678118654752f));
}

template<int EPI>
__global__ __launch_bounds__(256) void sgemm_kernel(
    const float* __restrict__ A, const float* __restrict__ B,
    float* __restrict__ C, int M, int N, int K,
    const float* __restrict__ bias,
    const float* __restrict__ r1, const float* __restrict__ r2)
{
    __shared__ float As[16][128];
    __shared__ float Bs[16][128];

    const int tid  = threadIdx.x;
    const int row0 = blockIdx.y * 128;
    const int col0 = blockIdx.x * 128;

    float acc[8][8];
#pragma unroll
    for (int i = 0; i < 8; i++)
#pragma unroll
        for (int j = 0; j < 8; j++) acc[i][j] = 0.f;

    const int ty = (tid >> 4) << 3;   // 0..120
    const int tx = (tid & 15) << 3;   // 0..120

    for (int k0 = 0; k0 < K; k0 += 16) {
        // load A tile (128 rows x 16 cols) -> As transposed [16][128]
#pragma unroll
        for (int j = 0; j < 2; j++) {
            int id = tid + j * 256;          // 0..511 float4 ids
            int r  = id >> 2;                // 0..127
            int c4 = id & 3;                 // 0..3
            float4 av = *(const float4*)(A + (size_t)(row0 + r) * K + k0 + c4 * 4);
            As[c4 * 4 + 0][r] = av.x;
            As[c4 * 4 + 1][r] = av.y;
            As[c4 * 4 + 2][r] = av.z;
            As[c4 * 4 + 3][r] = av.w;
        }
        // load B tile (16 rows x 128 cols)
#pragma unroll
        for (int j = 0; j < 2; j++) {
            int id = tid + j * 256;
            int r  = id >> 5;                // 0..15
            int c4 = id & 31;                // 0..31
            *(float4*)&Bs[r][c4 * 4] =
                *(const float4*)(B + (size_t)(k0 + r) * N + col0 + c4 * 4);
        }
        __syncthreads();

#pragma unroll
        for (int kk = 0; kk < 16; kk++) {
            float a[8], bb[8];
            *(float4*)(a)      = *(const float4*)&As[kk][ty];
            *(float4*)(a + 4)  = *(const float4*)&As[kk][ty + 4];
            *(float4*)(bb)     = *(const float4*)&Bs[kk][tx];
            *(float4*)(bb + 4) = *(const float4*)&Bs[kk][tx + 4];
#pragma unroll
            for (int i = 0; i < 8; i++)
#pragma unroll
                for (int j = 0; j < 8; j++)
                    acc[i][j] = fmaf(a[i], bb[j], acc[i][j]);
        }
        __syncthreads();
    }

    // epilogue (vectorized float4 store)
#pragma unroll
    for (int i = 0; i < 8; i++) {
        int r = row0 + ty + i;
#pragma unroll
        for (int j4 = 0; j4 < 2; j4++) {
            int c = col0 + tx + j4 * 4;
            size_t idx = (size_t)r * N + c;
            float o[4];
#pragma unroll
            for (int j = 0; j < 4; j++) {
                float v = acc[i][j4 * 4 + j];
                if (EPI == 1) v = v + bias[c + j] + r1[idx + j] + r2[idx + j];
                else if (EPI == 2) v = gelu_exact(v + bias[c + j]);
                else if (EPI == 3) v = v + bias[c + j] + r1[idx + j];
                o[j] = v;
            }
            *(float4*)&C[idx] = *(float4*)o;
        }
    }
}

// ======================= Flash attention =======================
// one thread per query row; block = 128 query rows of one (b,h);
// 32-key tiles staged in SMEM; online softmax, fp32.
__global__ __launch_bounds__(128) void attn_kernel(
    const float* __restrict__ qkv, float* __restrict__ out)
{
    __shared__ float Ks[32][64];
    __shared__ float Vs[32][64];

    const int bh = blockIdx.y;
    const int b  = bh / NHEAD;
    const int h  = bh % NHEAD;
    const int t  = threadIdx.x;
    const int n  = blockIdx.x * 128 + t;

    const float* qr = qkv + (size_t)(b * SEQ + n) * QKVW + h * HDIM;
    float q[HDIM];
#pragma unroll
    for (int d = 0; d < HDIM; d += 4) {
        float4 qq = *(const float4*)(qr + d);
        q[d + 0] = qq.x * 0.125f;   // 1/sqrt(64)
        q[d + 1] = qq.y * 0.125f;
        q[d + 2] = qq.z * 0.125f;
        q[d + 3] = qq.w * 0.125f;
    }

    float o[HDIM];
#pragma unroll
    for (int d = 0; d < HDIM; d++) o[d] = 0.f;
    float m = -1e30f, l = 0.f;

    for (int key0 = 0; key0 < SEQ; key0 += 32) {
        __syncthreads();
        // stage 32x64 K and V tiles (512 float4 each, 4 per thread)
#pragma unroll
        for (int j = 0; j < 4; j++) {
            int id = t + j * 128;            // 0..511
            int r  = id >> 4;                // 0..31
            int c  = (id & 15) << 2;         // 0..60
            const float* kb = qkv + (size_t)(b * SEQ + key0 + r) * QKVW + EMB + h * HDIM + c;
            *(float4*)&Ks[r][c] = *(const float4*)kb;
            *(float4*)&Vs[r][c] = *(const float4*)(kb + EMB);
        }
        __syncthreads();

        float s[32];
        float tmax = -1e30f;
#pragma unroll
        for (int kk = 0; kk < 32; kk++) {
            const float4* kr = (const float4*)Ks[kk];
            float a = 0.f;
#pragma unroll
            for (int i = 0; i < 16; i++) {
                float4 kv = kr[i];
                a = fmaf(q[4*i+0], kv.x, a);
                a = fmaf(q[4*i+1], kv.y, a);
                a = fmaf(q[4*i+2], kv.z, a);
                a = fmaf(q[4*i+3], kv.w, a);
            }
            s[kk] = a;
            tmax = fmaxf(tmax, a);
        }
        float newm = fmaxf(m, tmax);
        float corr = __expf(m - newm);
        m = newm;
        l *= corr;
#pragma unroll
        for (int d = 0; d < HDIM; d++) o[d] *= corr;

#pragma unroll
        for (int kk = 0; kk < 32; kk++) {
            float p = __expf(s[kk] - m);
            l += p;
            const float4* vr = (const float4*)Vs[kk];
#pragma unroll
            for (int i = 0; i < 16; i++) {
                float4 vv = vr[i];
                o[4*i+0] = fmaf(p, vv.x, o[4*i+0]);
                o[4*i+1] = fmaf(p, vv.y, o[4*i+1]);
                o[4*i+2] = fmaf(p, vv.z, o[4*i+2]);
                o[4*i+3] = fmaf(p, vv.w, o[4*i+3]);
            }
        }
    }

    float inv = 1.0f / l;
    float* orow = out + (size_t)(b * SEQ + n) * EMB + h * HDIM;
#pragma unroll
    for (int d = 0; d < HDIM; d += 4) {
        float4 ov;
        ov.x = o[d + 0] * inv;
        ov.y = o[d + 1] * inv;
        ov.z = o[d + 2] * inv;
        ov.w = o[d + 3] * inv;
        *(float4*)(orow + d) = ov;
    }
}

// ======================= launch =======================
extern "C" void kernel_launch(void* const* d_in, const int* in_sizes, int n_in,
                              void* d_out, int out_size)
{
    const float* x     = (const float*)d_in[0];
    const float* ln1_g = (const float*)d_in[1];
    const float* ln1_b = (const float*)d_in[2];
    const float* w_qkv = (const float*)d_in[3];
    const float* w_out = (const float*)d_in[4];
    const float* b_out = (const float*)d_in[5];
    const float* ln2_g = (const float*)d_in[6];
    const float* ln2_b = (const float*)d_in[7];
    const float* w1    = (const float*)d_in[8];
    const float* b1    = (const float*)d_in[9];
    const float* w2    = (const float*)d_in[10];
    const float* b2    = (const float*)d_in[11];
    float* out = (float*)d_out;

    float *h, *qkvb, *attn, *x2, *mid;
    cudaGetSymbolAddress((void**)&h,    g_h);
    cudaGetSymbolAddress((void**)&qkvb, g_qkv);
    cudaGetSymbolAddress((void**)&attn, g_attn);
    cudaGetSymbolAddress((void**)&x2,   g_x2);
    cudaGetSymbolAddress((void**)&mid,  g_mid);

    // 1) h = LN1(x)
    ln_kernel<<<NROWS, 256>>>(x, ln1_g, ln1_b, h);
    // 2) qkv = h @ w_qkv
    {
        dim3 g(QKVW / 128, NROWS / 128);
        sgemm_kernel<0><<<g, 256>>>(h, w_qkv, qkvb, NROWS, QKVW, EMB,
                                    nullptr, nullptr, nullptr);
    }
    // 3) attention
    {
        dim3 g(SEQ / 128, BATCH * NHEAD);
        attn_kernel<<<g, 128>>>(qkvb, attn);
    }
    // 4) x2 = x + h + (attn @ w_out + b_out)
    {
        dim3 g(EMB / 128, NROWS / 128);
        sgemm_kernel<1><<<g, 256>>>(attn, w_out, x2, NROWS, EMB, EMB,
                                    b_out, x, h);
    }
    // 5) h = LN2(x2)   (reuse buffer)
    ln_kernel<<<NROWS, 256>>>(x2, ln2_g, ln2_b, h);
    // 6) mid = gelu(h @ w1 + b1)
    {
        dim3 g(MLPD / 128, NROWS / 128);
        sgemm_kernel<2><<<g, 256>>>(h, w1, mid, NROWS, MLPD, EMB,
                                    b1, nullptr, nullptr);
    }
    // 7) out = x2 + (mid @ w2 + b2)
    {
        dim3 g(EMB / 128, NROWS / 128);
        sgemm_kernel<3><<<g, 256>>>(mid, w2, out, NROWS, EMB, MLPD,
                                    b2, x2, nullptr);
    }
}

// round 9
// speedup vs baseline: 1.1728x; 1.1728x over previous
#include <cuda_runtime.h>
#include <stdint.h>
#include <math.h>

#define BATCH 4
#define SEQ   1024
#define EMB   768
#define NHEAD 12
#define HDIM  64
#define MLPD  3072
#define NROWS (BATCH*SEQ)   // 4096
#define QKVW  (3*EMB)       // 2304

// ---- scratch (device globals: no allocation allowed) ----
__device__ float g_h   [NROWS*EMB];
__device__ float g_qkv [NROWS*QKVW];
__device__ float g_attn[NROWS*EMB];
__device__ float g_x2  [NROWS*EMB];
__device__ float g_mid [NROWS*MLPD];

// ======================= LayerNorm =======================
__global__ __launch_bounds__(256) void ln_kernel(
    const float* __restrict__ x, const float* __restrict__ g,
    const float* __restrict__ b, float* __restrict__ out)
{
    int row = blockIdx.x;
    const float* xr = x + (size_t)row * EMB;
    float* orow = out + (size_t)row * EMB;
    int t = threadIdx.x;

    float v[3];
    float s = 0.f, s2 = 0.f;
#pragma unroll
    for (int i = 0; i < 3; i++) {
        v[i] = xr[t + i * 256];
        s  += v[i];
        s2 += v[i] * v[i];
    }
#pragma unroll
    for (int o = 16; o; o >>= 1) {
        s  += __shfl_xor_sync(0xffffffffu, s,  o);
        s2 += __shfl_xor_sync(0xffffffffu, s2, o);
    }
    __shared__ float red[2][8];
    if ((t & 31) == 0) { red[0][t >> 5] = s; red[1][t >> 5] = s2; }
    __syncthreads();
    s = 0.f; s2 = 0.f;
#pragma unroll
    for (int i = 0; i < 8; i++) { s += red[0][i]; s2 += red[1][i]; }

    const float inv_n = 1.0f / (float)EMB;
    float mu  = s * inv_n;
    float var = fmaxf(s2 * inv_n - mu * mu, 0.f);
    float rs  = rsqrtf(var + 1e-5f);
#pragma unroll
    for (int i = 0; i < 3; i++) {
        int c = t + i * 256;
        orow[c] = (v[i] - mu) * rs * g[c] + b[c];
    }
}

// ======================= TF32 tensor-core GEMM =======================
// C[M,N] = A[M,K] @ B[K,N], 3xTF32 compensated (near-fp32 accuracy).
// 128x128x16 CTA tile, 8 warps (2x4), 64x32 warp tile, m16n8k8 mma,
// cp.async double-buffered smem.
__device__ __forceinline__ float gelu_exact(float v) {
    return 0.5f * v * (1.0f + erff(v * 0.70710678118654752f));
}

__device__ __forceinline__ unsigned f2tf(float x) {
    unsigned u;
    asm("cvt.rna.tf32.f32 %0, %1;" : "=r"(u) : "f"(x));
    return u;
}

__device__ __forceinline__ void mma8(float c[4],
    unsigned a0, unsigned a1, unsigned a2, unsigned a3,
    unsigned b0, unsigned b1)
{
    asm volatile(
        "mma.sync.aligned.m16n8k8.row.col.f32.tf32.tf32.f32 "
        "{%0,%1,%2,%3}, {%4,%5,%6,%7}, {%8,%9}, {%0,%1,%2,%3};"
        : "+f"(c[0]), "+f"(c[1]), "+f"(c[2]), "+f"(c[3])
        : "r"(a0), "r"(a1), "r"(a2), "r"(a3), "r"(b0), "r"(b1));
}

__device__ __forceinline__ void cp16(void* dst, const void* src) {
    unsigned sa = (unsigned)__cvta_generic_to_shared(dst);
    asm volatile("cp.async.cg.shared.global [%0], [%1], 16;" :: "r"(sa), "l"(src));
}

template<int EPI>
__global__ __launch_bounds__(256, 1) void tgemm_kernel(
    const float* __restrict__ A, const float* __restrict__ B,
    float* __restrict__ C, int M, int N, int K,
    const float* __restrict__ bias,
    const float* __restrict__ r1, const float* __restrict__ r2)
{
    // A tile stored [m][k] with pad 4 -> bank = (20m + k) % 32 conflict-free
    // B tile stored [k][n] with pad 8 -> bank = (8k + n) % 32 conflict-free
    __shared__ float As[2][128][20];
    __shared__ float Bs[2][16][136];

    const int tid  = threadIdx.x;
    const int lane = tid & 31;
    const int warp = tid >> 5;
    const int g    = lane >> 2;     // 0..7
    const int tg   = lane & 3;      // 0..3
    const int wm0  = (warp >> 2) * 64;  // 0 or 64
    const int wn0  = (warp & 3) * 32;   // 0,32,64,96
    const int row0 = blockIdx.y * 128;
    const int col0 = blockIdx.x * 128;

    float acc[4][4][4];
#pragma unroll
    for (int i = 0; i < 4; i++)
#pragma unroll
        for (int j = 0; j < 4; j++)
#pragma unroll
            for (int q = 0; q < 4; q++) acc[i][j][q] = 0.f;

    const int T = K >> 4;

    // ---- stage tile t into buffer buf ----
    auto issue = [&](int t, int buf) {
        const int k0 = t << 4;
#pragma unroll
        for (int j = 0; j < 2; j++) {
            int id = tid + j * 256;       // 0..511
            int ra = id >> 2, ca = (id & 3) << 2;   // A: 128 rows x 4 chunks
            cp16(&As[buf][ra][ca], A + (size_t)(row0 + ra) * K + k0 + ca);
            int rb = id >> 5, cb = (id & 31) << 2;  // B: 16 rows x 32 chunks
            cp16(&Bs[buf][rb][cb], B + (size_t)(k0 + rb) * N + col0 + cb);
        }
        asm volatile("cp.async.commit_group;" ::: "memory");
    };

    issue(0, 0);

    for (int t = 0; t < T; t++) {
        if (t + 1 < T) {
            issue(t + 1, (t + 1) & 1);
            asm volatile("cp.async.wait_group 1;" ::: "memory");
        } else {
            asm volatile("cp.async.wait_group 0;" ::: "memory");
        }
        __syncthreads();

        const int buf = t & 1;
#pragma unroll
        for (int kk = 0; kk < 16; kk += 8) {
            unsigned ah[4][4], al[4][4];
#pragma unroll
            for (int mi = 0; mi < 4; mi++) {
                const int r = wm0 + mi * 16;
                float x0 = As[buf][r + g    ][kk + tg    ];
                float x1 = As[buf][r + g + 8][kk + tg    ];
                float x2 = As[buf][r + g    ][kk + tg + 4];
                float x3 = As[buf][r + g + 8][kk + tg + 4];
                ah[mi][0] = f2tf(x0); al[mi][0] = f2tf(x0 - __uint_as_float(ah[mi][0]));
                ah[mi][1] = f2tf(x1); al[mi][1] = f2tf(x1 - __uint_as_float(ah[mi][1]));
                ah[mi][2] = f2tf(x2); al[mi][2] = f2tf(x2 - __uint_as_float(ah[mi][2]));
                ah[mi][3] = f2tf(x3); al[mi][3] = f2tf(x3 - __uint_as_float(ah[mi][3]));
            }
            unsigned bh[4][2], bl[4][2];
#pragma unroll
            for (int ni = 0; ni < 4; ni++) {
                const int cn = wn0 + ni * 8 + g;
                float y0 = Bs[buf][kk + tg    ][cn];
                float y1 = Bs[buf][kk + tg + 4][cn];
                bh[ni][0] = f2tf(y0); bl[ni][0] = f2tf(y0 - __uint_as_float(bh[ni][0]));
                bh[ni][1] = f2tf(y1); bl[ni][1] = f2tf(y1 - __uint_as_float(bh[ni][1]));
            }
#pragma unroll
            for (int mi = 0; mi < 4; mi++)
#pragma unroll
                for (int ni = 0; ni < 4; ni++) {
                    mma8(acc[mi][ni], ah[mi][0], ah[mi][1], ah[mi][2], ah[mi][3],
                         bh[ni][0], bh[ni][1]);
                    mma8(acc[mi][ni], ah[mi][0], ah[mi][1], ah[mi][2], ah[mi][3],
                         bl[ni][0], bl[ni][1]);
                    mma8(acc[mi][ni], al[mi][0], al[mi][1], al[mi][2], al[mi][3],
                         bh[ni][0], bh[ni][1]);
                }
        }
        __syncthreads();
    }

    // ---- epilogue ----
#pragma unroll
    for (int mi = 0; mi < 4; mi++) {
#pragma unroll
        for (int ni = 0; ni < 4; ni++) {
            const int c = col0 + wn0 + ni * 8 + tg * 2;
#pragma unroll
            for (int h = 0; h < 2; h++) {
                const int r = row0 + wm0 + mi * 16 + g + h * 8;
                const size_t idx = (size_t)r * N + c;
                float v0 = acc[mi][ni][h * 2 + 0];
                float v1 = acc[mi][ni][h * 2 + 1];
                if (EPI == 1) {
                    v0 += bias[c]     + r1[idx]     + r2[idx];
                    v1 += bias[c + 1] + r1[idx + 1] + r2[idx + 1];
                } else if (EPI == 2) {
                    v0 = gelu_exact(v0 + bias[c]);
                    v1 = gelu_exact(v1 + bias[c + 1]);
                } else if (EPI == 3) {
                    v0 += bias[c]     + r1[idx];
                    v1 += bias[c + 1] + r1[idx + 1];
                }
                float2 o = make_float2(v0, v1);
                *(float2*)&C[idx] = o;
            }
        }
    }
}

// ======================= Flash attention (fp32) =======================
__global__ __launch_bounds__(128) void attn_kernel(
    const float* __restrict__ qkv, float* __restrict__ out)
{
    __shared__ float Ks[32][64];
    __shared__ float Vs[32][64];

    const int bh = blockIdx.y;
    const int b  = bh / NHEAD;
    const int h  = bh % NHEAD;
    const int t  = threadIdx.x;
    const int n  = blockIdx.x * 128 + t;

    const float* qr = qkv + (size_t)(b * SEQ + n) * QKVW + h * HDIM;
    float q[HDIM];
#pragma unroll
    for (int d = 0; d < HDIM; d += 4) {
        float4 qq = *(const float4*)(qr + d);
        q[d + 0] = qq.x * 0.125f;
        q[d + 1] = qq.y * 0.125f;
        q[d + 2] = qq.z * 0.125f;
        q[d + 3] = qq.w * 0.125f;
    }

    float o[HDIM];
#pragma unroll
    for (int d = 0; d < HDIM; d++) o[d] = 0.f;
    float m = -1e30f, l = 0.f;

    for (int key0 = 0; key0 < SEQ; key0 += 32) {
        __syncthreads();
#pragma unroll
        for (int j = 0; j < 4; j++) {
            int id = t + j * 128;
            int r  = id >> 4;
            int c  = (id & 15) << 2;
            const float* kb = qkv + (size_t)(b * SEQ + key0 + r) * QKVW + EMB + h * HDIM + c;
            *(float4*)&Ks[r][c] = *(const float4*)kb;
            *(float4*)&Vs[r][c] = *(const float4*)(kb + EMB);
        }
        __syncthreads();

        float s[32];
        float tmax = -1e30f;
#pragma unroll
        for (int kk = 0; kk < 32; kk++) {
            const float4* kr = (const float4*)Ks[kk];
            float a = 0.f;
#pragma unroll
            for (int i = 0; i < 16; i++) {
                float4 kv = kr[i];
                a = fmaf(q[4*i+0], kv.x, a);
                a = fmaf(q[4*i+1], kv.y, a);
                a = fmaf(q[4*i+2], kv.z, a);
                a = fmaf(q[4*i+3], kv.w, a);
            }
            s[kk] = a;
            tmax = fmaxf(tmax, a);
        }
        float newm = fmaxf(m, tmax);
        float corr = __expf(m - newm);
        m = newm;
        l *= corr;
#pragma unroll
        for (int d = 0; d < HDIM; d++) o[d] *= corr;

#pragma unroll
        for (int kk = 0; kk < 32; kk++) {
            float p = __expf(s[kk] - m);
            l += p;
            const float4* vr = (const float4*)Vs[kk];
#pragma unroll
            for (int i = 0; i < 16; i++) {
                float4 vv = vr[i];
                o[4*i+0] = fmaf(p, vv.x, o[4*i+0]);
                o[4*i+1] = fmaf(p, vv.y, o[4*i+1]);
                o[4*i+2] = fmaf(p, vv.z, o[4*i+2]);
                o[4*i+3] = fmaf(p, vv.w, o[4*i+3]);
            }
        }
    }

    float inv = 1.0f / l;
    float* orow = out + (size_t)(b * SEQ + n) * EMB + h * HDIM;
#pragma unroll
    for (int d = 0; d < HDIM; d += 4) {
        float4 ov;
        ov.x = o[d + 0] * inv;
        ov.y = o[d + 1] * inv;
        ov.z = o[d + 2] * inv;
        ov.w = o[d + 3] * inv;
        *(float4*)(orow + d) = ov;
    }
}

// ======================= launch =======================
extern "C" void kernel_launch(void* const* d_in, const int* in_sizes, int n_in,
                              void* d_out, int out_size)
{
    const float* x     = (const float*)d_in[0];
    const float* ln1_g = (const float*)d_in[1];
    const float* ln1_b = (const float*)d_in[2];
    const float* w_qkv = (const float*)d_in[3];
    const float* w_out = (const float*)d_in[4];
    const float* b_out = (const float*)d_in[5];
    const float* ln2_g = (const float*)d_in[6];
    const float* ln2_b = (const float*)d_in[7];
    const float* w1    = (const float*)d_in[8];
    const float* b1    = (const float*)d_in[9];
    const float* w2    = (const float*)d_in[10];
    const float* b2    = (const float*)d_in[11];
    float* out = (float*)d_out;

    float *h, *qkvb, *attn, *x2, *mid;
    cudaGetSymbolAddress((void**)&h,    g_h);
    cudaGetSymbolAddress((void**)&qkvb, g_qkv);
    cudaGetSymbolAddress((void**)&attn, g_attn);
    cudaGetSymbolAddress((void**)&x2,   g_x2);
    cudaGetSymbolAddress((void**)&mid,  g_mid);

    // 1) h = LN1(x)
    ln_kernel<<<NROWS, 256>>>(x, ln1_g, ln1_b, h);
    // 2) qkv = h @ w_qkv
    {
        dim3 g(QKVW / 128, NROWS / 128);
        tgemm_kernel<0><<<g, 256>>>(h, w_qkv, qkvb, NROWS, QKVW, EMB,
                                    nullptr, nullptr, nullptr);
    }
    // 3) attention
    {
        dim3 g(SEQ / 128, BATCH * NHEAD);
        attn_kernel<<<g, 128>>>(qkvb, attn);
    }
    // 4) x2 = x + h + (attn @ w_out + b_out)
    {
        dim3 g(EMB / 128, NROWS / 128);
        tgemm_kernel<1><<<g, 256>>>(attn, w_out, x2, NROWS, EMB, EMB,
                                    b_out, x, h);
    }
    // 5) h = LN2(x2)
    ln_kernel<<<NROWS, 256>>>(x2, ln2_g, ln2_b, h);
    // 6) mid = gelu(h @ w1 + b1)
    {
        dim3 g(MLPD / 128, NROWS / 128);
        tgemm_kernel<2><<<g, 256>>>(h, w1, mid, NROWS, MLPD, EMB,
                                    b1, nullptr, nullptr);
    }
    // 7) out = x2 + (mid @ w2 + b2)
    {
        dim3 g(EMB / 128, NROWS / 128);
        tgemm_kernel<3><<<g, 256>>>(mid, w2, out, NROWS, EMB, MLPD,
                                    b2, x2, nullptr);
    }
}